// round 8
// baseline (speedup 1.0000x reference)
#include <cuda_runtime.h>

#define BZ 2
#define NN 512
#define CI 16
#define CO 16
#define HH 64

#define ATILE  128               // 4 a's per thread: a, a+32, a+64, a+96
#define BGRP   4
#define BSPLIT 128
#define BCHUNK (NN / BSPLIT)     // 4 b's per CTA = one group, single stage
// per-b smem slot: 1024 G floats + 16 B2 floats + 8 pad.
// stride 1048 words mod 32 banks = 24 -> bb offsets land in disjoint banks.
#define GSTR   1048

__device__ float g_G[BZ * NN * CO * HH];   // [z][b][i][h]  (4 MB)
__device__ float g_B2[BZ * NN * CO];       // [z][b][i]

// gelu (tanh approximation == jax.nn.gelu default):
//   gelu(x) = x * sigmoid(2*sqrt(2/pi)*(x + 0.044715 x^3))
__device__ __forceinline__ float gelu_fast(float x) {
    const float K = -(2.0f * 0.7978845608028654f * 1.4426950408889634f); // -2*sqrt(2/pi)*log2(e)
    float x2 = x * x;
    float p  = x * fmaf(0.044715f, x2, 1.0f) * K;   // exponent in log2 domain
    float e;  asm("ex2.approx.f32 %0, %1;" : "=f"(e) : "f"(p));
    float d = 1.0f + e;
    float r;  asm("rcp.approx.f32 %0, %1;" : "=f"(r) : "f"(d));
    return x * r;
}

// ---------------------------------------------------------------------------
// Kernel 1: G[z,b,i,h] = sum_j W2[i*16+j,h] * f[z,b,j];  B2[z,b,i] likewise.
// ---------------------------------------------------------------------------
__global__ void precompute_G(const float* __restrict__ features,
                             const float* __restrict__ W2,
                             const float* __restrict__ b2)
{
    __shared__ float fs[CI];
    const int zb = blockIdx.x;
    const int t  = threadIdx.x;
    if (t < CI) fs[t] = features[zb * CI + t];
    __syncthreads();

    const int i = t >> 4, hq = t & 15;
    float4 acc = make_float4(0.f, 0.f, 0.f, 0.f);
#pragma unroll
    for (int j = 0; j < CI; j++) {
        const float4 w = reinterpret_cast<const float4*>(W2)[(i * CI + j) * (HH / 4) + hq];
        const float f = fs[j];
        acc.x = fmaf(f, w.x, acc.x);
        acc.y = fmaf(f, w.y, acc.y);
        acc.z = fmaf(f, w.z, acc.z);
        acc.w = fmaf(f, w.w, acc.w);
    }
    reinterpret_cast<float4*>(g_G)[(zb * CO + i) * (HH / 4) + hq] = acc;

    if (t < CO) {
        float s = 0.f;
#pragma unroll
        for (int j = 0; j < CI; j++) s = fmaf(b2[t * CI + j], fs[j], s);
        g_B2[zb * CO + t] = s;
    }
}

// ---------------------------------------------------------------------------
// Kernel 2: out[z,a,b,i] = sum_h gelu(MLP1(geom_b - geom_a))[h] * G[z,b,i,h] + B2
// 128 threads: thread = (a_lane = t>>2 owning 4 a's, bb = t&3 owning 1 b).
// Each G LDS.128 feeds 16 FMAs (4 per a x 4 a's). Single cp.async stage.
// ---------------------------------------------------------------------------
__global__ __launch_bounds__(128, 3) void ApplyKernel_main(
    const float* __restrict__ geom,
    const float* __restrict__ W1,
    const float* __restrict__ b1,
    float* __restrict__ out)
{
    __shared__ float4 W1s[HH];
    __shared__ float  b1s[HH];
    __shared__ __align__(16) float Gs[BGRP * GSTR];

    const int t  = threadIdx.x;
    const int z  = blockIdx.z;
    const int al = blockIdx.y * ATILE + (t >> 2);   // first a
    const int bb = t & 3;
    const int b  = blockIdx.x * BGRP + bb;

    if (t < HH) {
        W1s[t] = reinterpret_cast<const float4*>(W1)[t];
        b1s[t] = b1[t];
    }

    // stage G (4 b's) + B2 into smem via cp.async
    {
        const int bbase = blockIdx.x * BGRP;
        const float* src = &g_G[(size_t)(z * NN + bbase) * CO * HH];
#pragma unroll
        for (int k = 0; k < 8; k++) {
            int q = t + k * 128;            // 1024 float4 quads of G
            int qb = q >> 8;
            int rem = q & 255;
            unsigned dst = (unsigned)__cvta_generic_to_shared(&Gs[qb * GSTR + rem * 4]);
            asm volatile("cp.async.ca.shared.global [%0], [%1], 16;"
                         :: "r"(dst), "l"(src + qb * CO * HH + rem * 4));
        }
        if (t < 16) {                       // 16 float4 quads of B2
            int qb = t >> 2, iq = t & 3;
            const float* bsrc = &g_B2[(size_t)(z * NN + bbase + qb) * CO + iq * 4];
            unsigned dst = (unsigned)__cvta_generic_to_shared(
                &Gs[qb * GSTR + CO * HH + iq * 4]);
            asm volatile("cp.async.ca.shared.global [%0], [%1], 16;"
                         :: "r"(dst), "l"(bsrc));
        }
        asm volatile("cp.async.commit_group;");
    }

    // geometry for the 4 a's and 1 b (overlaps with cp.async in flight)
    float gax[4], gay[4], gaz[4];
#pragma unroll
    for (int k = 0; k < 4; k++) {
        const int a = al + k * 32;
        gax[k] = geom[(z * NN + a) * 3 + 0];
        gay[k] = geom[(z * NN + a) * 3 + 1];
        gaz[k] = geom[(z * NN + a) * 3 + 2];
    }
    const float gbx = __ldg(&geom[(z * NN + b) * 3 + 0]);
    const float gby = __ldg(&geom[(z * NN + b) * 3 + 1]);
    const float gbz = __ldg(&geom[(z * NN + b) * 3 + 2]);

    float dx[4], dy[4], dz[4], nrm[4];
#pragma unroll
    for (int k = 0; k < 4; k++) {
        dx[k] = gbx - gax[k];
        dy[k] = gby - gay[k];
        dz[k] = gbz - gaz[k];
        const float r2 = fmaf(dx[k], dx[k], fmaf(dy[k], dy[k], dz[k] * dz[k])) + 1e-12f;
        asm("sqrt.approx.f32 %0, %1;" : "=f"(nrm[k]) : "f"(r2));
    }

    asm volatile("cp.async.wait_group 0;");
    __syncthreads();   // tile + W1s visible

    const float* gsb = &Gs[bb * GSTR];

    float acc[4][CO];
#pragma unroll
    for (int iq = 0; iq < 4; iq++) {
        const float4 v = *reinterpret_cast<const float4*>(&gsb[CO * HH + iq * 4]);
#pragma unroll
        for (int k = 0; k < 4; k++) {
            acc[k][iq * 4 + 0] = v.x; acc[k][iq * 4 + 1] = v.y;
            acc[k][iq * 4 + 2] = v.z; acc[k][iq * 4 + 3] = v.w;
        }
    }

#pragma unroll
    for (int hq = 0; hq < 16; hq++) {
        float hv[4][4];
#pragma unroll
        for (int c = 0; c < 4; c++) {
            const int h = hq * 4 + c;
            const float4 w = W1s[h];
            const float bw = b1s[h];
#pragma unroll
            for (int k = 0; k < 4; k++) {
                const float x = fmaf(dx[k], w.x, fmaf(dy[k], w.y,
                                fmaf(dz[k], w.z, fmaf(nrm[k], w.w, bw))));
                hv[k][c] = gelu_fast(x);
            }
        }
#pragma unroll
        for (int i = 0; i < CO; i++) {
            const float4 g = *reinterpret_cast<const float4*>(&gsb[i * HH + hq * 4]);
#pragma unroll
            for (int k = 0; k < 4; k++) {
                acc[k][i] = fmaf(hv[k][0], g.x, fmaf(hv[k][1], g.y,
                            fmaf(hv[k][2], g.z, fmaf(hv[k][3], g.w, acc[k][i]))));
            }
        }
    }

#pragma unroll
    for (int k = 0; k < 4; k++) {
        const int a = al + k * 32;
        float* op = &out[((size_t)(z * NN + a) * NN + b) * CO];
#pragma unroll
        for (int iq = 0; iq < 4; iq++) {
            reinterpret_cast<float4*>(op)[iq] =
                make_float4(acc[k][iq * 4 + 0], acc[k][iq * 4 + 1],
                            acc[k][iq * 4 + 2], acc[k][iq * 4 + 3]);
        }
    }
}

extern "C" void kernel_launch(void* const* d_in, const int* in_sizes, int n_in,
                              void* d_out, int out_size) {
    const float* features = (const float*)d_in[0];
    const float* geometry = (const float*)d_in[1];
    const float* W1       = (const float*)d_in[2];
    const float* b1       = (const float*)d_in[3];
    const float* W2       = (const float*)d_in[4];
    const float* b2       = (const float*)d_in[5];
    float* out = (float*)d_out;

    precompute_G<<<BZ * NN, 256>>>(features, W2, b2);

    dim3 grid(BSPLIT, NN / ATILE, BZ);
    ApplyKernel_main<<<grid, 128>>>(geometry, W1, b1, out);
}